// round 1
// baseline (speedup 1.0000x reference)
#include <cuda_runtime.h>
#include <math.h>

// ---------------------------------------------------------------------------
// resCNN: 3 locally-connected conv layers (kernel==stride, disjoint patches)
//         + tanh, then Linear(514,2) + softmax. B = 4096.
//
// Layout strategy: transpose x once to [CHW, B] (batch fastest). All
// intermediates stored [Cout, i, j, B]. Every LC layer then becomes, per
// output location, a GEMM  [B x K] * [K x Cout]  with coalesced A loads.
// Compute uses packed fma.rn.f32x2 (2 samples per 64-bit reg) to reach the
// full 128 FMA/cyc/SM fp32 rate on sm_103a.
// ---------------------------------------------------------------------------

#define BATCH 4096

using u64 = unsigned long long;

// Scratch (device globals — no allocations allowed in kernel_launch)
__device__ float g_xT[21600u * BATCH];           // [6*60*60, B]   354 MB
__device__ float g_h0[32u * 20 * 20 * BATCH];    // [32,20,20,B]   210 MB
__device__ float g_h1[64u * 10 * 10 * BATCH];    // [64,10,10,B]   105 MB
__device__ float g_h2[512u * BATCH];             // [512, B]       8.4 MB

__device__ __forceinline__ u64 ffma2(u64 a, u64 b, u64 c) {
    u64 d;
    asm("fma.rn.f32x2 %0, %1, %2, %3;" : "=l"(d) : "l"(a), "l"(b), "l"(c));
    return d;
}

// ------------------------- transpose: [B,CHW] -> [CHW,B] -------------------
__global__ void transpose_kernel(const float* __restrict__ in,
                                 float* __restrict__ out) {
    __shared__ float tile[32][33];
    const int bx = blockIdx.x * 32;   // chw base
    const int by = blockIdx.y * 32;   // batch base
    const int tx = threadIdx.x;       // 0..31
    const int ty = threadIdx.y;       // 0..7
    #pragma unroll
    for (int r = 0; r < 32; r += 8)
        tile[ty + r][tx] = in[(size_t)(by + ty + r) * 21600 + (bx + tx)];
    __syncthreads();
    #pragma unroll
    for (int r = 0; r < 32; r += 8)
        out[(size_t)(bx + ty + r) * BATCH + (by + tx)] = tile[tx][ty + r];
}

// ------------------------- locally connected layer -------------------------
// Per location (li,lj): Out[o,li,lj,b] = tanh( sum_m A[row(m),b]*W[o,m] + bias )
// A is [CIN*HIN*HIN, B]; W is [HOUT*HOUT, COUT, K]; bias [HOUT*HOUT, COUT].
// Block: one location x SAMPLES batch x COUT_TILE outputs.
// Thread tile: TMP sample-pairs (f32x2) x TN outputs.
template<int CIN, int HIN, int KH, int KW, int COUT, int HOUT,
         int COUT_TILE, int SAMPLES, int TMP, int TN, int KT>
__global__ void __launch_bounds__(256)
lc_layer(const float* __restrict__ A, const float* __restrict__ Wt,
         const float* __restrict__ bias, float* __restrict__ Out)
{
    constexpr int K     = CIN * KH * KW;
    constexpr int PAIRS = SAMPLES / 2;
    constexpr int PG    = PAIRS / TMP;       // pair groups (threads along batch)
    constexpr int OG    = COUT_TILE / TN;    // output groups
    static_assert(PG * OG == 256, "thread decomposition");
    static_assert(K % KT == 0, "K tiling");

    const int loc   = blockIdx.y;
    const int li    = loc / HOUT;
    const int lj    = loc % HOUT;
    const int b0    = blockIdx.x * SAMPLES;
    const int obase = blockIdx.z * COUT_TILE;

    __shared__ __align__(16) float sA[KT][SAMPLES];
    __shared__ __align__(16) u64   sW[KT][COUT_TILE];   // duplicated {w,w}

    const int tid = threadIdx.x;
    const int tpx = tid % PG;
    const int tpy = tid / PG;

    u64 acc[TMP][TN];
    #pragma unroll
    for (int m = 0; m < TMP; m++)
        #pragma unroll
        for (int n = 0; n < TN; n++) acc[m][n] = 0ull;

    const float* Wloc = Wt + ((size_t)loc * COUT + obase) * K;

    for (int kt = 0; kt < K; kt += KT) {
        // --- stage A tile (coalesced float4 loads, b-fastest layout) ---
        for (int idx = tid; idx < KT * SAMPLES / 4; idx += 256) {
            const int kk = idx / (SAMPLES / 4);
            const int s4 = idx % (SAMPLES / 4);
            const int m  = kt + kk;
            const int c  = m / (KH * KW);
            const int rm = m % (KH * KW);
            const int r  = rm / KW;
            const int l  = rm % KW;
            const int row = (c * HIN + li * KH + r) * HIN + (lj * KW + l);
            *(float4*)&sA[kk][s4 * 4] =
                *(const float4*)(A + (size_t)row * BATCH + b0 + s4 * 4);
        }
        // --- stage W tile, duplicated into both f32x2 lanes ---
        for (int idx = tid; idx < KT * COUT_TILE; idx += 256) {
            const int kk = idx / COUT_TILE;
            const int o  = idx % COUT_TILE;
            const unsigned int wb =
                __float_as_uint(Wloc[(size_t)o * K + kt + kk]);
            sW[kk][o] = ((u64)wb << 32) | (u64)wb;
        }
        __syncthreads();

        #pragma unroll
        for (int kk = 0; kk < KT; kk++) {
            const u64* sa = (const u64*)sA[kk];
            u64 a[TMP];
            #pragma unroll
            for (int m = 0; m < TMP; m++) a[m] = sa[tpx + m * PG];
            u64 w[TN];
            #pragma unroll
            for (int n = 0; n < TN; n += 2) {
                ulonglong2 wp = *(const ulonglong2*)&sW[kk][tpy * TN + n];
                w[n] = wp.x; w[n + 1] = wp.y;
            }
            #pragma unroll
            for (int m = 0; m < TMP; m++)
                #pragma unroll
                for (int n = 0; n < TN; n++)
                    acc[m][n] = ffma2(a[m], w[n], acc[m][n]);
        }
        __syncthreads();
    }

    // --- epilogue: bias + tanh, store [o, li, lj, b] ---
    #pragma unroll
    for (int n = 0; n < TN; n++) {
        const int o = obase + tpy * TN + n;
        const float bv = bias[loc * COUT + o];
        const size_t outrow = (((size_t)o * HOUT + li) * HOUT + lj) * BATCH + b0;
        #pragma unroll
        for (int m = 0; m < TMP; m++) {
            float2 v;
            v.x = tanhf(__uint_as_float((unsigned)(acc[m][n] & 0xffffffffu)) + bv);
            v.y = tanhf(__uint_as_float((unsigned)(acc[m][n] >> 32)) + bv);
            *(float2*)&Out[outrow + (size_t)(tpx + m * PG) * 2] = v;
        }
    }
}

// ------------------------- classifier + softmax ----------------------------
__global__ void __launch_bounds__(256)
classifier_kernel(const float* __restrict__ h2,    // [512, B]
                  const float* __restrict__ info,  // [B, 2]
                  const float* __restrict__ Wc,    // [514, 2]
                  const float* __restrict__ bc,    // [2]
                  float* __restrict__ out)         // [B, 2]
{
    __shared__ float sW[514 * 2];
    const int tid = threadIdx.x;
    for (int i = tid; i < 514 * 2; i += 256) sW[i] = Wc[i];
    __syncthreads();

    const int b = blockIdx.x * 256 + tid;
    float l0 = bc[0], l1 = bc[1];
    #pragma unroll 8
    for (int f = 0; f < 512; f++) {
        const float v = h2[(size_t)f * BATCH + b];
        l0 = fmaf(v, sW[f * 2 + 0], l0);
        l1 = fmaf(v, sW[f * 2 + 1], l1);
    }
    const float2 iv = *(const float2*)(info + (size_t)b * 2);
    l0 = fmaf(iv.x, sW[512 * 2 + 0], fmaf(iv.y, sW[513 * 2 + 0], l0));
    l1 = fmaf(iv.x, sW[512 * 2 + 1], fmaf(iv.y, sW[513 * 2 + 1], l1));

    const float mx = fmaxf(l0, l1);
    const float e0 = __expf(l0 - mx);   // |arg| <= O(1); fast exp is plenty
    const float e1 = __expf(l1 - mx);
    const float inv = 1.0f / (e0 + e1);
    float2 o = make_float2(e0 * inv, e1 * inv);
    *(float2*)(out + (size_t)b * 2) = o;
}

// ---------------------------------------------------------------------------
extern "C" void kernel_launch(void* const* d_in, const int* in_sizes, int n_in,
                              void* d_out, int out_size) {
    const float* x    = (const float*)d_in[0];
    const float* info = (const float*)d_in[1];
    const float* W0   = (const float*)d_in[2];
    const float* B0   = (const float*)d_in[3];
    const float* W1   = (const float*)d_in[4];
    const float* B1   = (const float*)d_in[5];
    const float* W2   = (const float*)d_in[6];
    const float* B2   = (const float*)d_in[7];
    const float* Wc   = (const float*)d_in[8];
    const float* bc   = (const float*)d_in[9];
    float* out = (float*)d_out;

    float *xT, *h0, *h1, *h2;
    cudaGetSymbolAddress((void**)&xT, g_xT);
    cudaGetSymbolAddress((void**)&h0, g_h0);
    cudaGetSymbolAddress((void**)&h1, g_h1);
    cudaGetSymbolAddress((void**)&h2, g_h2);

    // 1) x [B,21600] -> xT [21600,B]
    transpose_kernel<<<dim3(21600 / 32, BATCH / 32), dim3(32, 8)>>>(x, xT);

    // 2) L0: 6x60x60 -> 32x20x20, k=3 (K=54).  400 locations.
    lc_layer<6, 60, 3, 3, 32, 20,  32, 256, 4, 4,  9>
        <<<dim3(BATCH / 256, 400, 1), 256>>>(xT, W0, B0, h0);

    // 3) L1: 32x20x20 -> 64x10x10, k=2 (K=128). 100 locations.
    lc_layer<32, 20, 2, 2, 64, 10,  64, 256, 4, 8, 16>
        <<<dim3(BATCH / 256, 100, 1), 256>>>(h0, W1, B1, h1);

    // 4) L2: 64x10x10 -> 128x2x2, k=5 (K=1600). 4 locations, Cout split x2.
    lc_layer<64, 10, 5, 5, 128, 2,  64, 128, 4, 4, 16>
        <<<dim3(BATCH / 128, 4, 2), 256>>>(h1, W2, B2, h2);

    // 5) classifier + softmax
    classifier_kernel<<<BATCH / 256, 256>>>(h2, info, Wc, bc, out);
}

// round 2
// speedup vs baseline: 1.0102x; 1.0102x over previous
#include <cuda_runtime.h>
#include <math.h>

// ---------------------------------------------------------------------------
// resCNN: 3 locally-connected conv layers (kernel==stride, disjoint patches)
//         + tanh, then Linear(514,2) + softmax. B = 4096.
//
// Layout strategy: transpose x once to [CHW, B] (batch fastest). All
// intermediates stored [Cout, i, j, B]. Every LC layer then becomes, per
// output location, a GEMM  [B x K] * [K x Cout]  with coalesced A loads.
// Compute uses packed fma.rn.f32x2 (2 samples per 64-bit reg) to reach the
// full 128 FMA/cyc/SM fp32 rate on sm_103a.
// ---------------------------------------------------------------------------

#define BATCH 4096

using u64 = unsigned long long;

// Scratch (device globals — no allocations allowed in kernel_launch)
__device__ float g_xT[21600u * BATCH];           // [6*60*60, B]   354 MB
__device__ float g_h0[32u * 20 * 20 * BATCH];    // [32,20,20,B]   210 MB
__device__ float g_h1[64u * 10 * 10 * BATCH];    // [64,10,10,B]   105 MB
__device__ float g_h2[512u * BATCH];             // [512, B]       8.4 MB

__device__ __forceinline__ u64 ffma2(u64 a, u64 b, u64 c) {
    u64 d;
    asm("fma.rn.f32x2 %0, %1, %2, %3;" : "=l"(d) : "l"(a), "l"(b), "l"(c));
    return d;
}

// ------------------------- transpose: [B,CHW] -> [CHW,B] -------------------
__global__ void transpose_kernel(const float* __restrict__ in,
                                 float* __restrict__ out) {
    __shared__ float tile[32][33];
    const int bx = blockIdx.x * 32;   // chw base
    const int by = blockIdx.y * 32;   // batch base
    const int tx = threadIdx.x;       // 0..31
    const int ty = threadIdx.y;       // 0..7
    #pragma unroll
    for (int r = 0; r < 32; r += 8)
        tile[ty + r][tx] = in[(size_t)(by + ty + r) * 21600 + (bx + tx)];
    __syncthreads();
    #pragma unroll
    for (int r = 0; r < 32; r += 8)
        out[(size_t)(bx + ty + r) * BATCH + (by + tx)] = tile[tx][ty + r];
}

// ------------------------- locally connected layer -------------------------
// Per location (li,lj): Out[o,li,lj,b] = tanh( sum_m A[row(m),b]*W[o,m] + bias )
// A is [CIN*HIN*HIN, B]; W is [HOUT*HOUT, COUT, K]; bias [HOUT*HOUT, COUT].
// Block: one location x SAMPLES batch x COUT_TILE outputs.
// Thread tile: TMP sample-pairs (f32x2) x TN outputs.
template<int CIN, int HIN, int KH, int KW, int COUT, int HOUT,
         int COUT_TILE, int SAMPLES, int TMP, int TN, int KT>
__global__ void __launch_bounds__(256)
lc_layer(const float* __restrict__ A, const float* __restrict__ Wt,
         const float* __restrict__ bias, float* __restrict__ Out)
{
    constexpr int K     = CIN * KH * KW;
    constexpr int PAIRS = SAMPLES / 2;
    constexpr int PG    = PAIRS / TMP;       // pair groups (threads along batch)
    constexpr int OG    = COUT_TILE / TN;    // output groups
    static_assert(PG * OG == 256, "thread decomposition");
    static_assert(K % KT == 0, "K tiling");

    const int loc   = blockIdx.y;
    const int li    = loc / HOUT;
    const int lj    = loc % HOUT;
    const int b0    = blockIdx.x * SAMPLES;
    const int obase = blockIdx.z * COUT_TILE;

    __shared__ __align__(16) float sA[KT][SAMPLES];
    __shared__ __align__(16) u64   sW[KT][COUT_TILE];   // duplicated {w,w}

    const int tid = threadIdx.x;
    const int tpx = tid % PG;
    const int tpy = tid / PG;

    u64 acc[TMP][TN];
    #pragma unroll
    for (int m = 0; m < TMP; m++)
        #pragma unroll
        for (int n = 0; n < TN; n++) acc[m][n] = 0ull;

    const float* Wloc = Wt + ((size_t)loc * COUT + obase) * K;

    for (int kt = 0; kt < K; kt += KT) {
        // --- stage A tile (coalesced float4 loads, b-fastest layout) ---
        for (int idx = tid; idx < KT * SAMPLES / 4; idx += 256) {
            const int kk = idx / (SAMPLES / 4);
            const int s4 = idx % (SAMPLES / 4);
            const int m  = kt + kk;
            const int c  = m / (KH * KW);
            const int rm = m % (KH * KW);
            const int r  = rm / KW;
            const int l  = rm % KW;
            const int row = (c * HIN + li * KH + r) * HIN + (lj * KW + l);
            *(float4*)&sA[kk][s4 * 4] =
                *(const float4*)(A + (size_t)row * BATCH + b0 + s4 * 4);
        }
        // --- stage W tile, duplicated into both f32x2 lanes ---
        for (int idx = tid; idx < KT * COUT_TILE; idx += 256) {
            const int kk = idx / COUT_TILE;
            const int o  = idx % COUT_TILE;
            const unsigned int wb =
                __float_as_uint(Wloc[(size_t)o * K + kt + kk]);
            sW[kk][o] = ((u64)wb << 32) | (u64)wb;
        }
        __syncthreads();

        #pragma unroll
        for (int kk = 0; kk < KT; kk++) {
            const u64* sa = (const u64*)sA[kk];
            u64 a[TMP];
            #pragma unroll
            for (int m = 0; m < TMP; m++) a[m] = sa[tpx + m * PG];
            u64 w[TN];
            #pragma unroll
            for (int n = 0; n < TN; n += 2) {
                ulonglong2 wp = *(const ulonglong2*)&sW[kk][tpy * TN + n];
                w[n] = wp.x; w[n + 1] = wp.y;
            }
            #pragma unroll
            for (int m = 0; m < TMP; m++)
                #pragma unroll
                for (int n = 0; n < TN; n++)
                    acc[m][n] = ffma2(a[m], w[n], acc[m][n]);
        }
        __syncthreads();
    }

    // --- epilogue: bias + tanh, store [o, li, lj, b] ---
    #pragma unroll
    for (int n = 0; n < TN; n++) {
        const int o = obase + tpy * TN + n;
        const float bv = bias[loc * COUT + o];
        const size_t outrow = (((size_t)o * HOUT + li) * HOUT + lj) * BATCH + b0;
        #pragma unroll
        for (int m = 0; m < TMP; m++) {
            float2 v;
            v.x = tanhf(__uint_as_float((unsigned)(acc[m][n] & 0xffffffffu)) + bv);
            v.y = tanhf(__uint_as_float((unsigned)(acc[m][n] >> 32)) + bv);
            *(float2*)&Out[outrow + (size_t)(tpx + m * PG) * 2] = v;
        }
    }
}

// ------------------------- classifier + softmax ----------------------------
__global__ void __launch_bounds__(256)
classifier_kernel(const float* __restrict__ h2,    // [512, B]
                  const float* __restrict__ info,  // [B, 2]
                  const float* __restrict__ Wc,    // [514, 2]
                  const float* __restrict__ bc,    // [2]
                  float* __restrict__ out)         // [B, 2]
{
    __shared__ float sW[514 * 2];
    const int tid = threadIdx.x;
    for (int i = tid; i < 514 * 2; i += 256) sW[i] = Wc[i];
    __syncthreads();

    const int b = blockIdx.x * 256 + tid;
    float l0 = bc[0], l1 = bc[1];
    #pragma unroll 8
    for (int f = 0; f < 512; f++) {
        const float v = h2[(size_t)f * BATCH + b];
        l0 = fmaf(v, sW[f * 2 + 0], l0);
        l1 = fmaf(v, sW[f * 2 + 1], l1);
    }
    const float2 iv = *(const float2*)(info + (size_t)b * 2);
    l0 = fmaf(iv.x, sW[512 * 2 + 0], fmaf(iv.y, sW[513 * 2 + 0], l0));
    l1 = fmaf(iv.x, sW[512 * 2 + 1], fmaf(iv.y, sW[513 * 2 + 1], l1));

    const float mx = fmaxf(l0, l1);
    const float e0 = __expf(l0 - mx);   // |arg| <= O(1); fast exp is plenty
    const float e1 = __expf(l1 - mx);
    const float inv = 1.0f / (e0 + e1);
    float2 o = make_float2(e0 * inv, e1 * inv);
    *(float2*)(out + (size_t)b * 2) = o;
}

// ---------------------------------------------------------------------------
extern "C" void kernel_launch(void* const* d_in, const int* in_sizes, int n_in,
                              void* d_out, int out_size) {
    const float* x    = (const float*)d_in[0];
    const float* info = (const float*)d_in[1];
    const float* W0   = (const float*)d_in[2];
    const float* B0   = (const float*)d_in[3];
    const float* W1   = (const float*)d_in[4];
    const float* B1   = (const float*)d_in[5];
    const float* W2   = (const float*)d_in[6];
    const float* B2   = (const float*)d_in[7];
    const float* Wc   = (const float*)d_in[8];
    const float* bc   = (const float*)d_in[9];
    float* out = (float*)d_out;

    float *xT, *h0, *h1, *h2;
    cudaGetSymbolAddress((void**)&xT, g_xT);
    cudaGetSymbolAddress((void**)&h0, g_h0);
    cudaGetSymbolAddress((void**)&h1, g_h1);
    cudaGetSymbolAddress((void**)&h2, g_h2);

    // 1) x [B,21600] -> xT [21600,B]
    transpose_kernel<<<dim3(21600 / 32, BATCH / 32), dim3(32, 8)>>>(x, xT);

    // 2) L0: 6x60x60 -> 32x20x20, k=3 (K=54).  400 locations.
    lc_layer<6, 60, 3, 3, 32, 20,  32, 256, 4, 4,  9>
        <<<dim3(BATCH / 256, 400, 1), 256>>>(xT, W0, B0, h0);

    // 3) L1: 32x20x20 -> 64x10x10, k=2 (K=128). 100 locations.
    lc_layer<32, 20, 2, 2, 64, 10,  64, 256, 4, 8, 16>
        <<<dim3(BATCH / 256, 100, 1), 256>>>(h0, W1, B1, h1);

    // 4) L2: 64x10x10 -> 128x2x2, k=5 (K=1600). 4 locations, Cout split x2.
    lc_layer<64, 10, 5, 5, 128, 2,  64, 128, 4, 4, 16>
        <<<dim3(BATCH / 128, 4, 2), 256>>>(h1, W2, B2, h2);

    // 5) classifier + softmax
    classifier_kernel<<<BATCH / 256, 256>>>(h2, info, Wc, bc, out);
}

// round 3
// speedup vs baseline: 1.0105x; 1.0003x over previous
#include <cuda_runtime.h>
#include <math.h>

// ---------------------------------------------------------------------------
// resCNN: 3 locally-connected conv layers (kernel==stride, disjoint patches)
//         + tanh, then Linear(514,2) + softmax. B = 4096.
//
// Layout strategy: transpose x once to [CHW, B] (batch fastest). All
// intermediates stored [Cout, i, j, B]. Every LC layer then becomes, per
// output location, a GEMM  [B x K] * [K x Cout]  with coalesced A loads.
// Compute uses packed fma.rn.f32x2 (2 samples per 64-bit reg) to reach the
// full 128 FMA/cyc/SM fp32 rate on sm_103a.
// ---------------------------------------------------------------------------

#define BATCH 4096

using u64 = unsigned long long;

// Scratch (device globals — no allocations allowed in kernel_launch)
__device__ float g_xT[21600u * BATCH];           // [6*60*60, B]   354 MB
__device__ float g_h0[32u * 20 * 20 * BATCH];    // [32,20,20,B]   210 MB
__device__ float g_h1[64u * 10 * 10 * BATCH];    // [64,10,10,B]   105 MB
__device__ float g_h2[512u * BATCH];             // [512, B]       8.4 MB

__device__ __forceinline__ u64 ffma2(u64 a, u64 b, u64 c) {
    u64 d;
    asm("fma.rn.f32x2 %0, %1, %2, %3;" : "=l"(d) : "l"(a), "l"(b), "l"(c));
    return d;
}

// ------------------------- transpose: [B,CHW] -> [CHW,B] -------------------
__global__ void transpose_kernel(const float* __restrict__ in,
                                 float* __restrict__ out) {
    __shared__ float tile[32][33];
    const int bx = blockIdx.x * 32;   // chw base
    const int by = blockIdx.y * 32;   // batch base
    const int tx = threadIdx.x;       // 0..31
    const int ty = threadIdx.y;       // 0..7
    #pragma unroll
    for (int r = 0; r < 32; r += 8)
        tile[ty + r][tx] = in[(size_t)(by + ty + r) * 21600 + (bx + tx)];
    __syncthreads();
    #pragma unroll
    for (int r = 0; r < 32; r += 8)
        out[(size_t)(bx + ty + r) * BATCH + (by + tx)] = tile[tx][ty + r];
}

// ------------------------- locally connected layer -------------------------
// Per location (li,lj): Out[o,li,lj,b] = tanh( sum_m A[row(m),b]*W[o,m] + bias )
// A is [CIN*HIN*HIN, B]; W is [HOUT*HOUT, COUT, K]; bias [HOUT*HOUT, COUT].
// Block: one location x SAMPLES batch x COUT_TILE outputs.
// Thread tile: TMP sample-pairs (f32x2) x TN outputs.
template<int CIN, int HIN, int KH, int KW, int COUT, int HOUT,
         int COUT_TILE, int SAMPLES, int TMP, int TN, int KT>
__global__ void __launch_bounds__(256)
lc_layer(const float* __restrict__ A, const float* __restrict__ Wt,
         const float* __restrict__ bias, float* __restrict__ Out)
{
    constexpr int K     = CIN * KH * KW;
    constexpr int PAIRS = SAMPLES / 2;
    constexpr int PG    = PAIRS / TMP;       // pair groups (threads along batch)
    constexpr int OG    = COUT_TILE / TN;    // output groups
    static_assert(PG * OG == 256, "thread decomposition");
    static_assert(K % KT == 0, "K tiling");

    const int loc   = blockIdx.y;
    const int li    = loc / HOUT;
    const int lj    = loc % HOUT;
    const int b0    = blockIdx.x * SAMPLES;
    const int obase = blockIdx.z * COUT_TILE;

    __shared__ __align__(16) float sA[KT][SAMPLES];
    __shared__ __align__(16) u64   sW[KT][COUT_TILE];   // duplicated {w,w}

    const int tid = threadIdx.x;
    const int tpx = tid % PG;
    const int tpy = tid / PG;

    u64 acc[TMP][TN];
    #pragma unroll
    for (int m = 0; m < TMP; m++)
        #pragma unroll
        for (int n = 0; n < TN; n++) acc[m][n] = 0ull;

    const float* Wloc = Wt + ((size_t)loc * COUT + obase) * K;

    for (int kt = 0; kt < K; kt += KT) {
        // --- stage A tile (coalesced float4 loads, b-fastest layout) ---
        for (int idx = tid; idx < KT * SAMPLES / 4; idx += 256) {
            const int kk = idx / (SAMPLES / 4);
            const int s4 = idx % (SAMPLES / 4);
            const int m  = kt + kk;
            const int c  = m / (KH * KW);
            const int rm = m % (KH * KW);
            const int r  = rm / KW;
            const int l  = rm % KW;
            const int row = (c * HIN + li * KH + r) * HIN + (lj * KW + l);
            *(float4*)&sA[kk][s4 * 4] =
                *(const float4*)(A + (size_t)row * BATCH + b0 + s4 * 4);
        }
        // --- stage W tile, duplicated into both f32x2 lanes ---
        for (int idx = tid; idx < KT * COUT_TILE; idx += 256) {
            const int kk = idx / COUT_TILE;
            const int o  = idx % COUT_TILE;
            const unsigned int wb =
                __float_as_uint(Wloc[(size_t)o * K + kt + kk]);
            sW[kk][o] = ((u64)wb << 32) | (u64)wb;
        }
        __syncthreads();

        #pragma unroll
        for (int kk = 0; kk < KT; kk++) {
            const u64* sa = (const u64*)sA[kk];
            u64 a[TMP];
            #pragma unroll
            for (int m = 0; m < TMP; m++) a[m] = sa[tpx + m * PG];
            u64 w[TN];
            #pragma unroll
            for (int n = 0; n < TN; n += 2) {
                ulonglong2 wp = *(const ulonglong2*)&sW[kk][tpy * TN + n];
                w[n] = wp.x; w[n + 1] = wp.y;
            }
            #pragma unroll
            for (int m = 0; m < TMP; m++)
                #pragma unroll
                for (int n = 0; n < TN; n++)
                    acc[m][n] = ffma2(a[m], w[n], acc[m][n]);
        }
        __syncthreads();
    }

    // --- epilogue: bias + tanh, store [o, li, lj, b] ---
    #pragma unroll
    for (int n = 0; n < TN; n++) {
        const int o = obase + tpy * TN + n;
        const float bv = bias[loc * COUT + o];
        const size_t outrow = (((size_t)o * HOUT + li) * HOUT + lj) * BATCH + b0;
        #pragma unroll
        for (int m = 0; m < TMP; m++) {
            float2 v;
            v.x = tanhf(__uint_as_float((unsigned)(acc[m][n] & 0xffffffffu)) + bv);
            v.y = tanhf(__uint_as_float((unsigned)(acc[m][n] >> 32)) + bv);
            *(float2*)&Out[outrow + (size_t)(tpx + m * PG) * 2] = v;
        }
    }
}

// ------------------------- classifier + softmax ----------------------------
__global__ void __launch_bounds__(256)
classifier_kernel(const float* __restrict__ h2,    // [512, B]
                  const float* __restrict__ info,  // [B, 2]
                  const float* __restrict__ Wc,    // [514, 2]
                  const float* __restrict__ bc,    // [2]
                  float* __restrict__ out)         // [B, 2]
{
    __shared__ float sW[514 * 2];
    const int tid = threadIdx.x;
    for (int i = tid; i < 514 * 2; i += 256) sW[i] = Wc[i];
    __syncthreads();

    const int b = blockIdx.x * 256 + tid;
    float l0 = bc[0], l1 = bc[1];
    #pragma unroll 8
    for (int f = 0; f < 512; f++) {
        const float v = h2[(size_t)f * BATCH + b];
        l0 = fmaf(v, sW[f * 2 + 0], l0);
        l1 = fmaf(v, sW[f * 2 + 1], l1);
    }
    const float2 iv = *(const float2*)(info + (size_t)b * 2);
    l0 = fmaf(iv.x, sW[512 * 2 + 0], fmaf(iv.y, sW[513 * 2 + 0], l0));
    l1 = fmaf(iv.x, sW[512 * 2 + 1], fmaf(iv.y, sW[513 * 2 + 1], l1));

    const float mx = fmaxf(l0, l1);
    const float e0 = __expf(l0 - mx);   // |arg| <= O(1); fast exp is plenty
    const float e1 = __expf(l1 - mx);
    const float inv = 1.0f / (e0 + e1);
    float2 o = make_float2(e0 * inv, e1 * inv);
    *(float2*)(out + (size_t)b * 2) = o;
}

// ---------------------------------------------------------------------------
extern "C" void kernel_launch(void* const* d_in, const int* in_sizes, int n_in,
                              void* d_out, int out_size) {
    const float* x    = (const float*)d_in[0];
    const float* info = (const float*)d_in[1];
    const float* W0   = (const float*)d_in[2];
    const float* B0   = (const float*)d_in[3];
    const float* W1   = (const float*)d_in[4];
    const float* B1   = (const float*)d_in[5];
    const float* W2   = (const float*)d_in[6];
    const float* B2   = (const float*)d_in[7];
    const float* Wc   = (const float*)d_in[8];
    const float* bc   = (const float*)d_in[9];
    float* out = (float*)d_out;

    float *xT, *h0, *h1, *h2;
    cudaGetSymbolAddress((void**)&xT, g_xT);
    cudaGetSymbolAddress((void**)&h0, g_h0);
    cudaGetSymbolAddress((void**)&h1, g_h1);
    cudaGetSymbolAddress((void**)&h2, g_h2);

    // 1) x [B,21600] -> xT [21600,B]
    transpose_kernel<<<dim3(21600 / 32, BATCH / 32), dim3(32, 8)>>>(x, xT);

    // 2) L0: 6x60x60 -> 32x20x20, k=3 (K=54).  400 locations.
    lc_layer<6, 60, 3, 3, 32, 20,  32, 256, 4, 4,  9>
        <<<dim3(BATCH / 256, 400, 1), 256>>>(xT, W0, B0, h0);

    // 3) L1: 32x20x20 -> 64x10x10, k=2 (K=128). 100 locations.
    lc_layer<32, 20, 2, 2, 64, 10,  64, 256, 4, 8, 16>
        <<<dim3(BATCH / 256, 100, 1), 256>>>(h0, W1, B1, h1);

    // 4) L2: 64x10x10 -> 128x2x2, k=5 (K=1600). 4 locations, Cout split x2.
    lc_layer<64, 10, 5, 5, 128, 2,  64, 128, 4, 4, 16>
        <<<dim3(BATCH / 128, 4, 2), 256>>>(h1, W2, B2, h2);

    // 5) classifier + softmax
    classifier_kernel<<<BATCH / 256, 256>>>(h2, info, Wc, bc, out);
}